// round 15
// baseline (speedup 1.0000x reference)
#include <cuda_runtime.h>
#include <cuda_bf16.h>
#include <cstdint>

// Problem constants (VectorQuantizer_317827580710)
#define NB   32
#define D    256
#define HW   1024
#define N    32768
#define K    1024
#define QELEMS (N * D)
#define NPART  1024

#define TAU   3e-3f
#define CMAX  16
#define PR_ROWS 32

// Scratch (no device allocation allowed)
__device__ float g_wnorm[K];
__device__ float g_xnorm[N];
__device__ int   g_idx[N];
__device__ int   g_hist[K];
__device__ float g_partial[NPART];
__device__ int   g_ncand[N];
__device__ int   g_cand[N * CMAX];
__device__ __align__(16) __nv_bfloat16 g_xh[N * D];
__device__ __align__(16) float         g_xf[N * D];   // x transposed [n][d] fp32
__device__ __align__(16) __nv_bfloat16 g_wh[K * D];

// ---------------- PTX helpers (base compute_103 compatible only) ----------
__device__ __forceinline__ uint32_t smem_u32(const void* p) {
    uint32_t a;
    asm("{ .reg .u64 t; cvta.to.shared.u64 t, %1; cvt.u32.u64 %0, t; }"
        : "=r"(a) : "l"(p));
    return a;
}
__device__ __forceinline__ void cpa16(uint32_t dst, const void* src) {
    asm volatile("cp.async.ca.shared.global [%0], [%1], 16;" :: "r"(dst), "l"(src));
}
__device__ __forceinline__ void ldsm4(uint32_t* r, uint32_t a) {
    asm volatile("ldmatrix.sync.aligned.m8n8.x4.shared.b16 {%0,%1,%2,%3}, [%4];"
                 : "=r"(r[0]), "=r"(r[1]), "=r"(r[2]), "=r"(r[3]) : "r"(a));
}
__device__ __forceinline__ void ldsm2(uint32_t* r, uint32_t a) {
    asm volatile("ldmatrix.sync.aligned.m8n8.x2.shared.b16 {%0,%1}, [%2];"
                 : "=r"(r[0]), "=r"(r[1]) : "r"(a));
}
__device__ __forceinline__ void mma16816(float* c, const uint32_t* a, const uint32_t* b) {
    asm volatile(
        "mma.sync.aligned.m16n8k16.row.col.f32.bf16.bf16.f32 "
        "{%0,%1,%2,%3}, {%4,%5,%6,%7}, {%8,%9}, {%0,%1,%2,%3};"
        : "+f"(c[0]), "+f"(c[1]), "+f"(c[2]), "+f"(c[3])
        : "r"(a[0]), "r"(a[1]), "r"(a[2]), "r"(a[3]), "r"(b[0]), "r"(b[1]));
}

// monotone encode: lex-min over (dist, idx) == u64 min over key
__device__ __forceinline__ unsigned long long dist_key(float dist, int idx) {
    unsigned b = __float_as_uint(dist);
    unsigned u = (b & 0x80000000u) ? ~b : (b | 0x80000000u);
    return ((unsigned long long)u << 10) | (unsigned)idx;
}

__device__ __forceinline__ float block_reduce_f(float v, float* s) {
    int tid = threadIdx.x;
#pragma unroll
    for (int o = 16; o; o >>= 1) v += __shfl_down_sync(0xffffffffu, v, o);
    if ((tid & 31) == 0) s[tid >> 5] = v;
    __syncthreads();
    if (tid < 32) {
        v = (tid < 8) ? s[tid] : 0.f;
#pragma unroll
        for (int o = 4; o; o >>= 1) v += __shfl_down_sync(0xffffffffu, v, o);
    }
    return v;
}

// ---------------------------------------------------------------------------
// Kernel 0a: codebook norms (fp64->fp32) + bf16 convert + hist zero.
__global__ __launch_bounds__(256) void k_wcvt(const float* __restrict__ w) {
    __shared__ double sd[8];
    int c = blockIdx.x, tid = threadIdx.x;
    float v = w[c * D + tid];
    g_wh[c * D + tid] = __float2bfloat16(v);
    double s = (double)v * (double)v;
#pragma unroll
    for (int o = 16; o; o >>= 1) s += __shfl_down_sync(0xffffffffu, s, o);
    if ((tid & 31) == 0) sd[tid >> 5] = s;
    __syncthreads();
    if (tid == 0) {
        double t = 0.0;
        for (int i = 0; i < 8; i++) t += sd[i];
        g_wnorm[c] = (float)t;
        g_hist[c] = 0;
    }
}

// Kernel 0b: x -> [n][d] fp32 + bf16 (coalesced stores) + per-row ||x||^2.
// grid (HW/32, NB), block 256.
__global__ __launch_bounds__(256) void k_cvtx(const float* __restrict__ x) {
    __shared__ float t[256 * 32];   // t[d*32 + (hw ^ (d&31))]
    const int tid = threadIdx.x, lane = tid & 31, dg = tid >> 5;
    const int b = blockIdx.y, hwt = blockIdx.x;
    const float* xb = x + b * (D * HW) + hwt * 32;
#pragma unroll 8
    for (int i = 0; i < 32; i++) {
        int d = dg * 32 + i;
        t[d * 32 + (lane ^ (d & 31))] = xb[d * HW + lane];
    }
    __syncthreads();
    const int r = tid >> 3, kq = tid & 7;
    const long long n = (long long)b * HW + hwt * 32 + r;
    float* xf = g_xf + n * D;
    __nv_bfloat16* xh = g_xh + n * D;
    double s = 0.0;
#pragma unroll
    for (int j = 0; j < 8; j++) {
        int d0 = 4 * kq + 32 * j;     // per-row contiguous across kq lanes
        float4 v;
        v.x = t[(d0+0)*32 + (r ^ ((d0+0)&31))];
        v.y = t[(d0+1)*32 + (r ^ ((d0+1)&31))];
        v.z = t[(d0+2)*32 + (r ^ ((d0+2)&31))];
        v.w = t[(d0+3)*32 + (r ^ ((d0+3)&31))];
        *(float4*)(xf + d0) = v;
        s += (double)v.x*v.x + (double)v.y*v.y + (double)v.z*v.z + (double)v.w*v.w;
        __nv_bfloat162 p0 = __floats2bfloat162_rn(v.x, v.y);
        __nv_bfloat162 p1 = __floats2bfloat162_rn(v.z, v.w);
        uint2 u;
        u.x = *(uint32_t*)&p0; u.y = *(uint32_t*)&p1;
        *(uint2*)(xh + d0) = u;
    }
#pragma unroll
    for (int o = 4; o; o >>= 1) s += __shfl_down_sync(0xffffffffu, s, o, 8);
    if (kq == 0) g_xnorm[n] = (float)s;
}

// ---------------------------------------------------------------------------
// Kernel 1: bf16 mma.sync approx distance GEMM + two-pass candidate selection.
// grid = N/128 = 256 CTAs, block 256 (8 warps). Smem 96KB -> 2 CTAs/SM, 1 wave.
// Candidates -> per-row g_cand slots (smem counter only; NO global counter).
#define A_OFF 0
#define B_OFF 65536
#define KMMA_SMEM 98304

__global__ __launch_bounds__(256) void k_mma() {
    extern __shared__ char dsm[];
    __shared__ float rowmin_s[2][128];
    __shared__ float runmin_s[128];
    __shared__ int   cnt_s[128];

    const uint32_t smb = smem_u32(dsm);
    const int tid = threadIdx.x, lane = tid & 31, wid = tid >> 5;
    const int wr = wid & 3, wc = wid >> 2;     // rows 32*wr..+31, cols 32*wc..+31
    const int gid = lane >> 2, tig = lane & 3;
    const int n0 = blockIdx.x * 128;

    // ldmatrix lane addressing (XOR swizzle chunk^(row&7))
    const int arow = 32 * wr + (lane & 15);
    const uint32_t aRowBase = smb + A_OFF + arow * 512;
    const int ar7 = arow & 7, ach = lane >> 4;
    const int brow = 32 * wc + (lane & 7);
    const uint32_t bRowBase = smb + B_OFF + brow * 512;
    const int br7 = brow & 7, bch = (lane >> 3) & 1;

    // Prologue: resident A + B chunk 0
    for (int g = tid; g < 4096; g += 256) {
        int r = g >> 5, c = g & 31;
        cpa16(smb + A_OFF + r * 512 + ((c ^ (r & 7)) << 4), g_xh + (n0 + r) * D + c * 8);
    }
    for (int g = tid; g < 2048; g += 256) {
        int r = g >> 5, c = g & 31;
        cpa16(smb + B_OFF + r * 512 + ((c ^ (r & 7)) << 4), g_wh + r * D + c * 8);
    }
    asm volatile("cp.async.commit_group;");
    if (tid < 128) { runmin_s[tid] = 3.4e38f; cnt_s[tid] = 0; }
    asm volatile("cp.async.wait_group 0;" ::: "memory");
    __syncthreads();

    for (int cc = 0; cc < 16; cc++) {
        float acc[2][4][4];
#pragma unroll
        for (int mi = 0; mi < 2; mi++)
#pragma unroll
            for (int nj = 0; nj < 4; nj++)
#pragma unroll
                for (int q = 0; q < 4; q++) acc[mi][nj][q] = 0.f;

        // 128x64 dot tile
#pragma unroll 4
        for (int kt = 0; kt < 16; kt++) {
            uint32_t af[2][4], bf[4][2];
            const int ac = ((2 * kt + ach) ^ ar7) << 4;
            ldsm4(af[0], aRowBase + ac);
            ldsm4(af[1], aRowBase + 8192 + ac);
            const int bc = ((2 * kt + bch) ^ br7) << 4;
            ldsm2(bf[0], bRowBase + bc);
            ldsm2(bf[1], bRowBase + 4096 + bc);
            ldsm2(bf[2], bRowBase + 8192 + bc);
            ldsm2(bf[3], bRowBase + 12288 + bc);
#pragma unroll
            for (int mi = 0; mi < 2; mi++)
#pragma unroll
                for (int nj = 0; nj < 4; nj++) mma16816(acc[mi][nj], af[mi], bf[nj]);
        }

        // da = wnorm - 2*dot (in place) + per-thread row mins
#pragma unroll
        for (int nj = 0; nj < 4; nj++) {
            const int c0 = cc * 64 + 32 * wc + 8 * nj + 2 * tig;
            const float wn0 = __ldg(&g_wnorm[c0]);
            const float wn1 = __ldg(&g_wnorm[c0 + 1]);
#pragma unroll
            for (int mi = 0; mi < 2; mi++) {
                acc[mi][nj][0] = wn0 - 2.f * acc[mi][nj][0];
                acc[mi][nj][1] = wn1 - 2.f * acc[mi][nj][1];
                acc[mi][nj][2] = wn0 - 2.f * acc[mi][nj][2];
                acc[mi][nj][3] = wn1 - 2.f * acc[mi][nj][3];
            }
        }
        float rmin[2][2];
#pragma unroll
        for (int mi = 0; mi < 2; mi++) {
            rmin[mi][0] = fminf(fminf(acc[mi][0][0], acc[mi][0][1]),
                                fminf(acc[mi][1][0], acc[mi][1][1]));
            rmin[mi][0] = fminf(rmin[mi][0],
                          fminf(fminf(acc[mi][2][0], acc[mi][2][1]),
                                fminf(acc[mi][3][0], acc[mi][3][1])));
            rmin[mi][1] = fminf(fminf(acc[mi][0][2], acc[mi][0][3]),
                                fminf(acc[mi][1][2], acc[mi][1][3]));
            rmin[mi][1] = fminf(rmin[mi][1],
                          fminf(fminf(acc[mi][2][2], acc[mi][2][3]),
                                fminf(acc[mi][3][2], acc[mi][3][3])));
#pragma unroll
            for (int o = 1; o <= 2; o <<= 1) {
                rmin[mi][0] = fminf(rmin[mi][0], __shfl_xor_sync(0xffffffffu, rmin[mi][0], o));
                rmin[mi][1] = fminf(rmin[mi][1], __shfl_xor_sync(0xffffffffu, rmin[mi][1], o));
            }
            if (tig == 0) {
                rowmin_s[wc][32 * wr + 16 * mi + gid]     = rmin[mi][0];
                rowmin_s[wc][32 * wr + 16 * mi + gid + 8] = rmin[mi][1];
            }
        }
        __syncthreads();   // all MMA reads of B done; rowmin_s ready

        // Prefetch next B chunk (overlaps runmin update + appends)
        if (cc < 15) {
            for (int g = tid; g < 2048; g += 256) {
                int r = g >> 5, c = g & 31;
                cpa16(smb + B_OFF + r * 512 + ((c ^ (r & 7)) << 4),
                      g_wh + ((cc + 1) * 64 + r) * D + c * 8);
            }
            asm volatile("cp.async.commit_group;");
        }

        if (tid < 128) {
            float m = fminf(rowmin_s[0][tid], rowmin_s[1][tid]);
            if (m < runmin_s[tid]) runmin_s[tid] = m;
        }
        __syncthreads();

        // Append pass (two-pass: runmin already includes this chunk)
#pragma unroll
        for (int mi = 0; mi < 2; mi++)
#pragma unroll
            for (int h = 0; h < 2; h++) {
                const int row = 32 * wr + 16 * mi + gid + 8 * h;
                const float thr = runmin_s[row] + TAU;
#pragma unroll
                for (int nj = 0; nj < 4; nj++)
#pragma unroll
                    for (int q = 0; q < 2; q++) {
                        float v = acc[mi][nj][2 * h + q];
                        if (v < thr) {
                            int s = atomicAdd(&cnt_s[row], 1);
                            if (s < CMAX)
                                g_cand[(n0 + row) * CMAX + s] =
                                    cc * 64 + 32 * wc + 8 * nj + 2 * tig + q;
                        }
                    }
            }
        if (cc < 15) asm volatile("cp.async.wait_group 0;" ::: "memory");
        __syncthreads();
    }
    if (tid < 128) g_ncand[n0 + tid] = cnt_s[tid];
}

// ---------------------------------------------------------------------------
// Kernel 2: exact re-verification, block-staged. CTA = 32 rows; x rows staged
// in smem (pitch 257 -> conflict-free); one (row,cand) pair per thread;
// per-row winner via smem u64 atomicMin on lex key (deterministic).
// Overflow rows (~never): whole-CTA full scan, same kernel.
__global__ __launch_bounds__(256) void k_pair(const float* __restrict__ w) {
    __shared__ float xs[PR_ROWS][257];
    __shared__ float sxn[PR_ROWS];
    __shared__ unsigned long long best_s[PR_ROWS];
    __shared__ unsigned short work[PR_ROWS * CMAX];
    __shared__ int nwork;
    const int tid = threadIdx.x;
    const int n0 = blockIdx.x * PR_ROWS;

    for (int i = 0; i < PR_ROWS; i++)
        xs[i][tid] = g_xf[(long long)(n0 + i) * D + tid];
    if (tid == 0) nwork = 0;
    if (tid < PR_ROWS) { sxn[tid] = g_xnorm[n0 + tid]; best_s[tid] = ~0ULL; }
    __syncthreads();

    if (tid < PR_ROWS) {
        int nc = min(g_ncand[n0 + tid], CMAX);
        for (int s2 = 0; s2 < nc; s2++) {
            int p = atomicAdd(&nwork, 1);
            work[p] = (unsigned short)((tid << 10) | g_cand[(n0 + tid) * CMAX + s2]);
        }
    }
    __syncthreads();

    const int np = nwork;
    for (int i = tid; i < np; i += 256) {
        const int lr = work[i] >> 10, c = work[i] & 1023;
        const float* wr = w + c * D;
        float acc = 0.f;
#pragma unroll 8
        for (int k = 0; k < D; k += 4) {
            float4 wv = *(const float4*)(wr + k);
            acc = fmaf(xs[lr][k],     wv.x, acc);
            acc = fmaf(xs[lr][k + 1], wv.y, acc);
            acc = fmaf(xs[lr][k + 2], wv.z, acc);
            acc = fmaf(xs[lr][k + 3], wv.w, acc);
        }
        float t1 = sxn[lr] + g_wnorm[c];
        float dist = t1 - 2.f * acc;
        atomicMin(&best_s[lr], dist_key(dist, c));
    }

    // Overflow fallback: uniform branch per block
    for (int r2 = 0; r2 < PR_ROWS; r2++) {
        if (g_ncand[n0 + r2] > CMAX) {
            for (int c = tid; c < K; c += 256) {
                const float* wr = w + c * D;
                float acc = 0.f;
#pragma unroll 8
                for (int k = 0; k < D; k += 4) {
                    float4 wv = *(const float4*)(wr + k);
                    acc = fmaf(xs[r2][k],     wv.x, acc);
                    acc = fmaf(xs[r2][k + 1], wv.y, acc);
                    acc = fmaf(xs[r2][k + 2], wv.z, acc);
                    acc = fmaf(xs[r2][k + 3], wv.w, acc);
                }
                float t1 = sxn[r2] + g_wnorm[c];
                float dist = t1 - 2.f * acc;
                atomicMin(&best_s[r2], dist_key(dist, c));
            }
        }
    }
    __syncthreads();
    if (tid < PR_ROWS) g_idx[n0 + tid] = (int)(best_s[tid] & 1023u);
}

// ---------------------------------------------------------------------------
// Kernel 3: quantized_st = x + (q - x) in [B,C,H,W] layout + loss partials.
__global__ __launch_bounds__(256) void k_quant(const float* __restrict__ x,
                                               const float* __restrict__ w,
                                               float* __restrict__ outq) {
    __shared__ float4 Qs[32][64];
    __shared__ int sidx[32];
    __shared__ float sred[8];
    const int t = threadIdx.x;
    const int b = blockIdx.x >> 5;
    const int hw0 = (blockIdx.x & 31) << 5;
    if (t < 32) sidx[t] = g_idx[(b << 10) + hw0 + t];
    __syncthreads();

    const int r0 = t >> 6;
    const int c4 = t & 63;
#pragma unroll
    for (int j = 0; j < 8; ++j) {
        const int r = r0 + (j << 2);
        const float4* wr = (const float4*)(w + sidx[r] * D);
        Qs[r][c4 ^ r] = wr[c4];
    }
    __syncthreads();

    const int c = t & 31;
    const int s0 = t >> 5;
    const float* xb = x + b * (D * HW) + hw0 + c;
    float*       ob = outq + b * (D * HW) + hw0 + c;
    float accv = 0.f;
#pragma unroll
    for (int j = 0; j < 8; ++j) {
        const int s = s0 + (j << 3);
        float4 q = Qs[c][s ^ c];
        const int d = s << 2;
        float qq[4] = {q.x, q.y, q.z, q.w};
#pragma unroll
        for (int k2 = 0; k2 < 4; ++k2) {
            float xv = xb[(d + k2) * HW];
            float df = qq[k2] - xv;
            ob[(d + k2) * HW] = xv + df;
            accv += df * df;
        }
    }
    float v = block_reduce_f(accv, sred);
    if (t == 0) g_partial[blockIdx.x] = v;
}

// ---------------------------------------------------------------------------
// Kernel 4: one-hot encodings + exact int histogram.
// 64 floats (32 float2) per thread; warp-interleaved stores (2x128B per instr).
__global__ __launch_bounds__(256) void k_enc(float2* __restrict__ enc) {
    const int gid = blockIdx.x * 256 + threadIdx.x;   // < N*16
    const int n = gid >> 4, seg = gid & 15;
    const int idx = __ldg(&g_idx[n]);
    float2* p = enc + n * 512 + seg;
    int myslot = (((idx >> 1) & 15) == seg) ? ((idx >> 1) >> 4) : -1;
    float hx = 0.f, hy = 0.f;
    if (myslot >= 0) {
        if (idx & 1) hy = 1.f; else hx = 1.f;
        atomicAdd(&g_hist[idx], 1);
    }
#pragma unroll
    for (int j = 0; j < 32; j++) {
        float2 v = make_float2(j == myslot ? hx : 0.f, j == myslot ? hy : 0.f);
        p[16 * j] = v;
    }
}

// ---------------------------------------------------------------------------
// Kernel 5: finalize loss + perplexity.
__global__ __launch_bounds__(256) void k_final(float* __restrict__ out) {
    __shared__ double sd[8];
    int tid = threadIdx.x;

    double s = 0.0;
    for (int i = tid; i < NPART; i += 256) s += (double)g_partial[i];
#pragma unroll
    for (int o = 16; o; o >>= 1) s += __shfl_down_sync(0xffffffffu, s, o);
    if ((tid & 31) == 0) sd[tid >> 5] = s;
    __syncthreads();
    if (tid == 0) {
        double t = 0.0;
        for (int i = 0; i < 8; i++) t += sd[i];
        out[0] = (float)(t / (double)QELEMS * 1.25);
    }
    __syncthreads();

    double e = 0.0;
    for (int i = tid; i < K; i += 256) {
        double p = (double)g_hist[i] / (double)N;
        e += p * log(p + 1e-10);
    }
#pragma unroll
    for (int o = 16; o; o >>= 1) e += __shfl_down_sync(0xffffffffu, e, o);
    if ((tid & 31) == 0) sd[tid >> 5] = e;
    __syncthreads();
    if (tid == 0) {
        double t = 0.0;
        for (int i = 0; i < 8; i++) t += sd[i];
        out[1 + QELEMS] = (float)exp(-t);
    }
}

// ---------------------------------------------------------------------------
extern "C" void kernel_launch(void* const* d_in, const int* in_sizes, int n_in,
                              void* d_out, int out_size) {
    const float* x = (const float*)d_in[0];   // inputs [32,256,32,32]
    const float* w = (const float*)d_in[1];   // weight [1024,256]
    float* out = (float*)d_out;

    cudaFuncSetAttribute(k_mma, cudaFuncAttributeMaxDynamicSharedMemorySize, KMMA_SMEM);

    k_wcvt  <<<K, 256>>>(w);
    k_cvtx  <<<dim3(HW / 32, NB), 256>>>(x);
    k_mma   <<<N / 128, 256, KMMA_SMEM>>>();
    k_pair  <<<N / PR_ROWS, 256>>>(w);        // 4th launch -> ncu capture slot
    k_quant <<<NPART, 256>>>(x, w, out + 1);
    k_enc   <<<(N * 16) / 256, 256>>>((float2*)(out + 2 + QELEMS));
    k_final <<<1, 256>>>(out);
}

// round 16
// speedup vs baseline: 1.0064x; 1.0064x over previous
#include <cuda_runtime.h>
#include <cuda_bf16.h>
#include <cstdint>

// Problem constants (VectorQuantizer_317827580710)
#define NB   32
#define D    256
#define HW   1024
#define N    32768
#define K    1024
#define QELEMS (N * D)
#define NPART  1024

#define TAU   3e-3f
#define CMAX  16
#define PR_ROWS 32

// Scratch (no device allocation allowed)
__device__ float g_wnorm[K];
__device__ float g_xnorm[N];
__device__ int   g_idx[N];
__device__ int   g_hist[K];
__device__ float g_partial[NPART];
__device__ int   g_ncand[N];
__device__ int   g_cand[N * CMAX];
__device__ __align__(16) __nv_bfloat16 g_xh[N * D];
__device__ __align__(16) float         g_xf[N * D];   // x transposed [n][d] fp32
__device__ __align__(16) __nv_bfloat16 g_wh[K * D];

// ---------------- PTX helpers (base compute_103 compatible only) ----------
__device__ __forceinline__ uint32_t smem_u32(const void* p) {
    uint32_t a;
    asm("{ .reg .u64 t; cvta.to.shared.u64 t, %1; cvt.u32.u64 %0, t; }"
        : "=r"(a) : "l"(p));
    return a;
}
__device__ __forceinline__ void cpa16(uint32_t dst, const void* src) {
    asm volatile("cp.async.ca.shared.global [%0], [%1], 16;" :: "r"(dst), "l"(src));
}
__device__ __forceinline__ void ldsm4(uint32_t* r, uint32_t a) {
    asm volatile("ldmatrix.sync.aligned.m8n8.x4.shared.b16 {%0,%1,%2,%3}, [%4];"
                 : "=r"(r[0]), "=r"(r[1]), "=r"(r[2]), "=r"(r[3]) : "r"(a));
}
__device__ __forceinline__ void ldsm2(uint32_t* r, uint32_t a) {
    asm volatile("ldmatrix.sync.aligned.m8n8.x2.shared.b16 {%0,%1}, [%2];"
                 : "=r"(r[0]), "=r"(r[1]) : "r"(a));
}
__device__ __forceinline__ void mma16816(float* c, const uint32_t* a, const uint32_t* b) {
    asm volatile(
        "mma.sync.aligned.m16n8k16.row.col.f32.bf16.bf16.f32 "
        "{%0,%1,%2,%3}, {%4,%5,%6,%7}, {%8,%9}, {%0,%1,%2,%3};"
        : "+f"(c[0]), "+f"(c[1]), "+f"(c[2]), "+f"(c[3])
        : "r"(a[0]), "r"(a[1]), "r"(a[2]), "r"(a[3]), "r"(b[0]), "r"(b[1]));
}

// monotone encode: lex-min over (dist, idx) == u64 min over key
__device__ __forceinline__ unsigned long long dist_key(float dist, int idx) {
    unsigned b = __float_as_uint(dist);
    unsigned u = (b & 0x80000000u) ? ~b : (b | 0x80000000u);
    return ((unsigned long long)u << 10) | (unsigned)idx;
}

__device__ __forceinline__ float block_reduce_f(float v, float* s) {
    int tid = threadIdx.x;
#pragma unroll
    for (int o = 16; o; o >>= 1) v += __shfl_down_sync(0xffffffffu, v, o);
    if ((tid & 31) == 0) s[tid >> 5] = v;
    __syncthreads();
    if (tid < 32) {
        v = (tid < 8) ? s[tid] : 0.f;
#pragma unroll
        for (int o = 4; o; o >>= 1) v += __shfl_down_sync(0xffffffffu, v, o);
    }
    return v;
}

// ---------------------------------------------------------------------------
// Kernel 0a: codebook norms (fp64->fp32) + bf16 convert + hist zero.
__global__ __launch_bounds__(256) void k_wcvt(const float* __restrict__ w) {
    __shared__ double sd[8];
    int c = blockIdx.x, tid = threadIdx.x;
    float v = w[c * D + tid];
    g_wh[c * D + tid] = __float2bfloat16(v);
    double s = (double)v * (double)v;
#pragma unroll
    for (int o = 16; o; o >>= 1) s += __shfl_down_sync(0xffffffffu, s, o);
    if ((tid & 31) == 0) sd[tid >> 5] = s;
    __syncthreads();
    if (tid == 0) {
        double t = 0.0;
        for (int i = 0; i < 8; i++) t += sd[i];
        g_wnorm[c] = (float)t;
        g_hist[c] = 0;
    }
}

// Kernel 0b: x -> [n][d] fp32 + bf16 (coalesced stores) + per-row ||x||^2.
// grid (HW/32, NB), block 256.
__global__ __launch_bounds__(256) void k_cvtx(const float* __restrict__ x) {
    __shared__ float t[256 * 32];   // t[d*32 + (hw ^ (d&31))]
    const int tid = threadIdx.x, lane = tid & 31, dg = tid >> 5;
    const int b = blockIdx.y, hwt = blockIdx.x;
    const float* xb = x + b * (D * HW) + hwt * 32;
#pragma unroll 8
    for (int i = 0; i < 32; i++) {
        int d = dg * 32 + i;
        t[d * 32 + (lane ^ (d & 31))] = xb[d * HW + lane];
    }
    __syncthreads();
    const int r = tid >> 3, kq = tid & 7;
    const long long n = (long long)b * HW + hwt * 32 + r;
    float* xf = g_xf + n * D;
    __nv_bfloat16* xh = g_xh + n * D;
    double s = 0.0;
#pragma unroll
    for (int j = 0; j < 8; j++) {
        int d0 = 4 * kq + 32 * j;     // per-row contiguous across kq lanes
        float4 v;
        v.x = t[(d0+0)*32 + (r ^ ((d0+0)&31))];
        v.y = t[(d0+1)*32 + (r ^ ((d0+1)&31))];
        v.z = t[(d0+2)*32 + (r ^ ((d0+2)&31))];
        v.w = t[(d0+3)*32 + (r ^ ((d0+3)&31))];
        *(float4*)(xf + d0) = v;
        s += (double)v.x*v.x + (double)v.y*v.y + (double)v.z*v.z + (double)v.w*v.w;
        __nv_bfloat162 p0 = __floats2bfloat162_rn(v.x, v.y);
        __nv_bfloat162 p1 = __floats2bfloat162_rn(v.z, v.w);
        uint2 u;
        u.x = *(uint32_t*)&p0; u.y = *(uint32_t*)&p1;
        *(uint2*)(xh + d0) = u;
    }
#pragma unroll
    for (int o = 4; o; o >>= 1) s += __shfl_down_sync(0xffffffffu, s, o, 8);
    if (kq == 0) g_xnorm[n] = (float)s;
}

// ---------------------------------------------------------------------------
// Kernel 1: bf16 mma.sync approx distance GEMM + two-pass candidate selection.
// grid = N/128 = 256 CTAs, block 256 (8 warps). Smem 96KB -> 2 CTAs/SM, 1 wave.
// Candidates -> per-row g_cand slots (smem counter only; NO global counter).
#define A_OFF 0
#define B_OFF 65536
#define KMMA_SMEM 98304

__global__ __launch_bounds__(256) void k_mma() {
    extern __shared__ char dsm[];
    __shared__ float rowmin_s[2][128];
    __shared__ float runmin_s[128];
    __shared__ int   cnt_s[128];

    const uint32_t smb = smem_u32(dsm);
    const int tid = threadIdx.x, lane = tid & 31, wid = tid >> 5;
    const int wr = wid & 3, wc = wid >> 2;     // rows 32*wr..+31, cols 32*wc..+31
    const int gid = lane >> 2, tig = lane & 3;
    const int n0 = blockIdx.x * 128;

    // ldmatrix lane addressing (XOR swizzle chunk^(row&7))
    const int arow = 32 * wr + (lane & 15);
    const uint32_t aRowBase = smb + A_OFF + arow * 512;
    const int ar7 = arow & 7, ach = lane >> 4;
    const int brow = 32 * wc + (lane & 7);
    const uint32_t bRowBase = smb + B_OFF + brow * 512;
    const int br7 = brow & 7, bch = (lane >> 3) & 1;

    // Prologue: resident A + B chunk 0
    for (int g = tid; g < 4096; g += 256) {
        int r = g >> 5, c = g & 31;
        cpa16(smb + A_OFF + r * 512 + ((c ^ (r & 7)) << 4), g_xh + (n0 + r) * D + c * 8);
    }
    for (int g = tid; g < 2048; g += 256) {
        int r = g >> 5, c = g & 31;
        cpa16(smb + B_OFF + r * 512 + ((c ^ (r & 7)) << 4), g_wh + r * D + c * 8);
    }
    asm volatile("cp.async.commit_group;");
    if (tid < 128) { runmin_s[tid] = 3.4e38f; cnt_s[tid] = 0; }
    asm volatile("cp.async.wait_group 0;" ::: "memory");
    __syncthreads();

    for (int cc = 0; cc < 16; cc++) {
        float acc[2][4][4];
#pragma unroll
        for (int mi = 0; mi < 2; mi++)
#pragma unroll
            for (int nj = 0; nj < 4; nj++)
#pragma unroll
                for (int q = 0; q < 4; q++) acc[mi][nj][q] = 0.f;

        // 128x64 dot tile
#pragma unroll 4
        for (int kt = 0; kt < 16; kt++) {
            uint32_t af[2][4], bf[4][2];
            const int ac = ((2 * kt + ach) ^ ar7) << 4;
            ldsm4(af[0], aRowBase + ac);
            ldsm4(af[1], aRowBase + 8192 + ac);
            const int bc = ((2 * kt + bch) ^ br7) << 4;
            ldsm2(bf[0], bRowBase + bc);
            ldsm2(bf[1], bRowBase + 4096 + bc);
            ldsm2(bf[2], bRowBase + 8192 + bc);
            ldsm2(bf[3], bRowBase + 12288 + bc);
#pragma unroll
            for (int mi = 0; mi < 2; mi++)
#pragma unroll
                for (int nj = 0; nj < 4; nj++) mma16816(acc[mi][nj], af[mi], bf[nj]);
        }

        // da = wnorm - 2*dot (in place) + per-thread row mins
#pragma unroll
        for (int nj = 0; nj < 4; nj++) {
            const int c0 = cc * 64 + 32 * wc + 8 * nj + 2 * tig;
            const float wn0 = __ldg(&g_wnorm[c0]);
            const float wn1 = __ldg(&g_wnorm[c0 + 1]);
#pragma unroll
            for (int mi = 0; mi < 2; mi++) {
                acc[mi][nj][0] = wn0 - 2.f * acc[mi][nj][0];
                acc[mi][nj][1] = wn1 - 2.f * acc[mi][nj][1];
                acc[mi][nj][2] = wn0 - 2.f * acc[mi][nj][2];
                acc[mi][nj][3] = wn1 - 2.f * acc[mi][nj][3];
            }
        }
        float rmin[2][2];
#pragma unroll
        for (int mi = 0; mi < 2; mi++) {
            rmin[mi][0] = fminf(fminf(acc[mi][0][0], acc[mi][0][1]),
                                fminf(acc[mi][1][0], acc[mi][1][1]));
            rmin[mi][0] = fminf(rmin[mi][0],
                          fminf(fminf(acc[mi][2][0], acc[mi][2][1]),
                                fminf(acc[mi][3][0], acc[mi][3][1])));
            rmin[mi][1] = fminf(fminf(acc[mi][0][2], acc[mi][0][3]),
                                fminf(acc[mi][1][2], acc[mi][1][3]));
            rmin[mi][1] = fminf(rmin[mi][1],
                          fminf(fminf(acc[mi][2][2], acc[mi][2][3]),
                                fminf(acc[mi][3][2], acc[mi][3][3])));
#pragma unroll
            for (int o = 1; o <= 2; o <<= 1) {
                rmin[mi][0] = fminf(rmin[mi][0], __shfl_xor_sync(0xffffffffu, rmin[mi][0], o));
                rmin[mi][1] = fminf(rmin[mi][1], __shfl_xor_sync(0xffffffffu, rmin[mi][1], o));
            }
            if (tig == 0) {
                rowmin_s[wc][32 * wr + 16 * mi + gid]     = rmin[mi][0];
                rowmin_s[wc][32 * wr + 16 * mi + gid + 8] = rmin[mi][1];
            }
        }
        __syncthreads();   // all MMA reads of B done; rowmin_s ready

        // Prefetch next B chunk (overlaps runmin update + appends)
        if (cc < 15) {
            for (int g = tid; g < 2048; g += 256) {
                int r = g >> 5, c = g & 31;
                cpa16(smb + B_OFF + r * 512 + ((c ^ (r & 7)) << 4),
                      g_wh + ((cc + 1) * 64 + r) * D + c * 8);
            }
            asm volatile("cp.async.commit_group;");
        }

        if (tid < 128) {
            float m = fminf(rowmin_s[0][tid], rowmin_s[1][tid]);
            if (m < runmin_s[tid]) runmin_s[tid] = m;
        }
        __syncthreads();

        // Append pass (two-pass: runmin already includes this chunk)
#pragma unroll
        for (int mi = 0; mi < 2; mi++)
#pragma unroll
            for (int h = 0; h < 2; h++) {
                const int row = 32 * wr + 16 * mi + gid + 8 * h;
                const float thr = runmin_s[row] + TAU;
#pragma unroll
                for (int nj = 0; nj < 4; nj++)
#pragma unroll
                    for (int q = 0; q < 2; q++) {
                        float v = acc[mi][nj][2 * h + q];
                        if (v < thr) {
                            int s = atomicAdd(&cnt_s[row], 1);
                            if (s < CMAX)
                                g_cand[(n0 + row) * CMAX + s] =
                                    cc * 64 + 32 * wc + 8 * nj + 2 * tig + q;
                        }
                    }
            }
        if (cc < 15) asm volatile("cp.async.wait_group 0;" ::: "memory");
        __syncthreads();
    }
    if (tid < 128) g_ncand[n0 + tid] = cnt_s[tid];
}

// ---------------------------------------------------------------------------
// Kernel 2: exact re-verification, block-staged. CTA = 32 rows; x rows staged
// in smem (pitch 257 -> conflict-free); one (row,cand) pair per thread;
// per-row winner via smem u64 atomicMin on lex key (deterministic).
// Overflow rows (~never): whole-CTA full scan, same kernel.
__global__ __launch_bounds__(256) void k_pair(const float* __restrict__ w) {
    __shared__ float xs[PR_ROWS][257];
    __shared__ float sxn[PR_ROWS];
    __shared__ unsigned long long best_s[PR_ROWS];
    __shared__ unsigned short work[PR_ROWS * CMAX];
    __shared__ int nwork;
    const int tid = threadIdx.x;
    const int n0 = blockIdx.x * PR_ROWS;

    for (int i = 0; i < PR_ROWS; i++)
        xs[i][tid] = g_xf[(long long)(n0 + i) * D + tid];
    if (tid == 0) nwork = 0;
    if (tid < PR_ROWS) { sxn[tid] = g_xnorm[n0 + tid]; best_s[tid] = ~0ULL; }
    __syncthreads();

    if (tid < PR_ROWS) {
        int nc = min(g_ncand[n0 + tid], CMAX);
        for (int s2 = 0; s2 < nc; s2++) {
            int p = atomicAdd(&nwork, 1);
            work[p] = (unsigned short)((tid << 10) | g_cand[(n0 + tid) * CMAX + s2]);
        }
    }
    __syncthreads();

    const int np = nwork;
    for (int i = tid; i < np; i += 256) {
        const int lr = work[i] >> 10, c = work[i] & 1023;
        const float* wr = w + c * D;
        float acc = 0.f;
#pragma unroll 8
        for (int k = 0; k < D; k += 4) {
            float4 wv = *(const float4*)(wr + k);
            acc = fmaf(xs[lr][k],     wv.x, acc);
            acc = fmaf(xs[lr][k + 1], wv.y, acc);
            acc = fmaf(xs[lr][k + 2], wv.z, acc);
            acc = fmaf(xs[lr][k + 3], wv.w, acc);
        }
        float t1 = sxn[lr] + g_wnorm[c];
        float dist = t1 - 2.f * acc;
        atomicMin(&best_s[lr], dist_key(dist, c));
    }

    // Overflow fallback: uniform branch per block
    for (int r2 = 0; r2 < PR_ROWS; r2++) {
        if (g_ncand[n0 + r2] > CMAX) {
            for (int c = tid; c < K; c += 256) {
                const float* wr = w + c * D;
                float acc = 0.f;
#pragma unroll 8
                for (int k = 0; k < D; k += 4) {
                    float4 wv = *(const float4*)(wr + k);
                    acc = fmaf(xs[r2][k],     wv.x, acc);
                    acc = fmaf(xs[r2][k + 1], wv.y, acc);
                    acc = fmaf(xs[r2][k + 2], wv.z, acc);
                    acc = fmaf(xs[r2][k + 3], wv.w, acc);
                }
                float t1 = sxn[r2] + g_wnorm[c];
                float dist = t1 - 2.f * acc;
                atomicMin(&best_s[r2], dist_key(dist, c));
            }
        }
    }
    __syncthreads();
    if (tid < PR_ROWS) g_idx[n0 + tid] = (int)(best_s[tid] & 1023u);
}

// ---------------------------------------------------------------------------
// Kernel 3: quantized_st = x + (q - x) in [B,C,H,W] layout + loss partials.
__global__ __launch_bounds__(256) void k_quant(const float* __restrict__ x,
                                               const float* __restrict__ w,
                                               float* __restrict__ outq) {
    __shared__ float4 Qs[32][64];
    __shared__ int sidx[32];
    __shared__ float sred[8];
    const int t = threadIdx.x;
    const int b = blockIdx.x >> 5;
    const int hw0 = (blockIdx.x & 31) << 5;
    if (t < 32) sidx[t] = g_idx[(b << 10) + hw0 + t];
    __syncthreads();

    const int r0 = t >> 6;
    const int c4 = t & 63;
#pragma unroll
    for (int j = 0; j < 8; ++j) {
        const int r = r0 + (j << 2);
        const float4* wr = (const float4*)(w + sidx[r] * D);
        Qs[r][c4 ^ r] = wr[c4];
    }
    __syncthreads();

    const int c = t & 31;
    const int s0 = t >> 5;
    const float* xb = x + b * (D * HW) + hw0 + c;
    float*       ob = outq + b * (D * HW) + hw0 + c;
    float accv = 0.f;
#pragma unroll
    for (int j = 0; j < 8; ++j) {
        const int s = s0 + (j << 3);
        float4 q = Qs[c][s ^ c];
        const int d = s << 2;
        float qq[4] = {q.x, q.y, q.z, q.w};
#pragma unroll
        for (int k2 = 0; k2 < 4; ++k2) {
            float xv = xb[(d + k2) * HW];
            float df = qq[k2] - xv;
            ob[(d + k2) * HW] = xv + df;
            accv += df * df;
        }
    }
    float v = block_reduce_f(accv, sred);
    if (t == 0) g_partial[blockIdx.x] = v;
}

// ---------------------------------------------------------------------------
// Kernel 4: one-hot encodings + exact int histogram.
// 64 floats (32 float2) per thread; warp-interleaved stores (2x128B per instr).
__global__ __launch_bounds__(256) void k_enc(float2* __restrict__ enc) {
    const int gid = blockIdx.x * 256 + threadIdx.x;   // < N*16
    const int n = gid >> 4, seg = gid & 15;
    const int idx = __ldg(&g_idx[n]);
    float2* p = enc + n * 512 + seg;
    int myslot = (((idx >> 1) & 15) == seg) ? ((idx >> 1) >> 4) : -1;
    float hx = 0.f, hy = 0.f;
    if (myslot >= 0) {
        if (idx & 1) hy = 1.f; else hx = 1.f;
        atomicAdd(&g_hist[idx], 1);
    }
#pragma unroll
    for (int j = 0; j < 32; j++) {
        float2 v = make_float2(j == myslot ? hx : 0.f, j == myslot ? hy : 0.f);
        p[16 * j] = v;
    }
}

// ---------------------------------------------------------------------------
// Kernel 5: finalize loss + perplexity.
__global__ __launch_bounds__(256) void k_final(float* __restrict__ out) {
    __shared__ double sd[8];
    int tid = threadIdx.x;

    double s = 0.0;
    for (int i = tid; i < NPART; i += 256) s += (double)g_partial[i];
#pragma unroll
    for (int o = 16; o; o >>= 1) s += __shfl_down_sync(0xffffffffu, s, o);
    if ((tid & 31) == 0) sd[tid >> 5] = s;
    __syncthreads();
    if (tid == 0) {
        double t = 0.0;
        for (int i = 0; i < 8; i++) t += sd[i];
        out[0] = (float)(t / (double)QELEMS * 1.25);
    }
    __syncthreads();

    double e = 0.0;
    for (int i = tid; i < K; i += 256) {
        double p = (double)g_hist[i] / (double)N;
        e += p * log(p + 1e-10);
    }
#pragma unroll
    for (int o = 16; o; o >>= 1) e += __shfl_down_sync(0xffffffffu, e, o);
    if ((tid & 31) == 0) sd[tid >> 5] = e;
    __syncthreads();
    if (tid == 0) {
        double t = 0.0;
        for (int i = 0; i < 8; i++) t += sd[i];
        out[1 + QELEMS] = (float)exp(-t);
    }
}

// ---------------------------------------------------------------------------
extern "C" void kernel_launch(void* const* d_in, const int* in_sizes, int n_in,
                              void* d_out, int out_size) {
    const float* x = (const float*)d_in[0];   // inputs [32,256,32,32]
    const float* w = (const float*)d_in[1];   // weight [1024,256]
    float* out = (float*)d_out;

    cudaFuncSetAttribute(k_mma, cudaFuncAttributeMaxDynamicSharedMemorySize, KMMA_SMEM);

    k_wcvt  <<<K, 256>>>(w);
    k_cvtx  <<<dim3(HW / 32, NB), 256>>>(x);
    k_mma   <<<N / 128, 256, KMMA_SMEM>>>();
    k_pair  <<<N / PR_ROWS, 256>>>(w);        // 4th launch -> ncu capture slot
    k_quant <<<NPART, 256>>>(x, w, out + 1);
    k_enc   <<<(N * 16) / 256, 256>>>((float2*)(out + 2 + QELEMS));
    k_final <<<1, 256>>>(out);
}